// round 3
// baseline (speedup 1.0000x reference)
#include <cuda_runtime.h>
#include <math.h>

#define BB 8
#define NN 2048
#define DD 1024
#define H1 128
#define FF 28
#define DK 64
#define NSTEPS 4
#define BN (BB*NN)

// ---- scratch (static device globals; no runtime allocation) ----
static __device__ float  g_H[BN*H1];                  // gelu(X@W1^T+b1)   8 MB
static __device__ float  g_V[BN*DK];                  // X@Wv^T            4 MB
static __device__ float  g_Q[BN*DK];
static __device__ float  g_K[BN*DK];
static __device__ float  g_compat[(size_t)BB*NN*NN];  // 134 MB, lower triangle valid
static __device__ float  g_ccur[BN];                  // current charge c_t
static __device__ float4 g_cpack[BN];                 // packed (c1,c2,c3,c4), zeroed per launch
static __device__ float  g_M[BN];
static __device__ float  g_Zinv[BN];
static __device__ float  g_AV[BN*DK];                 // attn@V (normalized)

// ============================================================
// K1: fused GEMM  Y[16384,192] = X[16384,1024] @ [W1|Wv]^T
//     outputs: g_H (gelu applied, +b1) and g_V
// ============================================================
__global__ void __launch_bounds__(256) k1_gemm(const float* __restrict__ X,
        const float* __restrict__ w1, const float* __restrict__ b1,
        const float* __restrict__ wv) {
    __shared__ float Xs[32][68];    // [k][row]
    __shared__ float Ws[32][196];   // [k][out]
    const int t  = threadIdx.x;
    const int tx = t & 15, ty = t >> 4;
    const int r0 = blockIdx.x * 64;

    float acc[4][12];
    #pragma unroll
    for (int i = 0; i < 4; i++)
        #pragma unroll
        for (int j = 0; j < 12; j++) acc[i][j] = 0.f;

    for (int k0 = 0; k0 < DD; k0 += 32) {
        #pragma unroll
        for (int i = 0; i < 8; i++) {
            int idx = t + i*256;              // 0..2047
            int r = idx >> 5, kk = idx & 31;
            Xs[kk][r] = X[(size_t)(r0+r)*DD + k0 + kk];
        }
        #pragma unroll
        for (int i = 0; i < 24; i++) {
            int idx = t + i*256;              // 0..6143
            int o = idx >> 5, kk = idx & 31;
            Ws[kk][o] = (o < H1) ? w1[o*DD + k0 + kk] : wv[(o-H1)*DD + k0 + kk];
        }
        __syncthreads();
        #pragma unroll
        for (int k = 0; k < 32; k++) {
            float4 xv = *reinterpret_cast<const float4*>(&Xs[k][ty*4]);
            float xr[4] = {xv.x, xv.y, xv.z, xv.w};
            float wr[12];
            #pragma unroll
            for (int q = 0; q < 3; q++) {
                float4 w4 = *reinterpret_cast<const float4*>(&Ws[k][tx*12 + q*4]);
                wr[q*4+0] = w4.x; wr[q*4+1] = w4.y; wr[q*4+2] = w4.z; wr[q*4+3] = w4.w;
            }
            #pragma unroll
            for (int i = 0; i < 4; i++)
                #pragma unroll
                for (int j = 0; j < 12; j++)
                    acc[i][j] = fmaf(xr[i], wr[j], acc[i][j]);
        }
        __syncthreads();
    }
    #pragma unroll
    for (int i = 0; i < 4; i++) {
        int r = r0 + ty*4 + i;
        #pragma unroll
        for (int j = 0; j < 12; j++) {
            int o = tx*12 + j;
            float v = acc[i][j];
            if (o < H1) {
                v += b1[o];
                v = 0.5f * v * (1.f + erff(v * 0.7071067811865476f));  // exact gelu
                g_H[(size_t)r*H1 + o] = v;
            } else {
                g_V[(size_t)r*DK + (o - H1)] = v;
            }
        }
    }
}

// ============================================================
// K2: features = sigmoid(H@W2^T+b2); Q/K; charge0; zero g_cpack
// ============================================================
__global__ void __launch_bounds__(256) k2_feat(const float* __restrict__ w2,
        const float* __restrict__ b2, const float* __restrict__ wq,
        const float* __restrict__ wk, const float* __restrict__ wc,
        const float* __restrict__ bc) {
    __shared__ float Hs[8][H1];
    __shared__ float Fs[8][FF];
    int warp = threadIdx.x >> 5, lane = threadIdx.x & 31;
    int row = blockIdx.x * 8 + warp;

    for (int k = lane; k < H1; k += 32) Hs[warp][k] = g_H[(size_t)row*H1 + k];
    __syncwarp();
    if (lane < FF) {
        float s = b2[lane];
        #pragma unroll 4
        for (int k = 0; k < H1; k++) s = fmaf(Hs[warp][k], w2[lane*H1 + k], s);
        Fs[warp][lane] = 1.f / (1.f + __expf(-s));
    }
    __syncwarp();
    #pragma unroll
    for (int half = 0; half < 2; half++) {
        int d = lane + half*32;
        float q = 0.f, kv = 0.f;
        #pragma unroll
        for (int j = 0; j < FF; j++) {
            float fv = Fs[warp][j];
            q  = fmaf(fv, wq[d*FF + j], q);
            kv = fmaf(fv, wk[d*FF + j], kv);
        }
        g_Q[(size_t)row*DK + d] = q;
        g_K[(size_t)row*DK + d] = kv;
    }
    if (lane == 0) {
        float s = bc[0];
        #pragma unroll
        for (int j = 0; j < FF; j++) s = fmaf(Fs[warp][j], wc[j], s);
        g_ccur[row] = 1.f / (1.f + __expf(-s));
        g_cpack[row] = make_float4(0.f, 0.f, 0.f, 0.f);   // per-launch reset (determinism)
    }
}

// ============================================================
// K3: compat[b,n,m] = Q[b,n]·K[b,m] / 8, lower-triangle tiles only
// ============================================================
__global__ void __launch_bounds__(256) k3_compat() {
    int tc = blockIdx.x, tr = blockIdx.y, b = blockIdx.z;
    if (tc > tr) return;
    __shared__ float Qs[DK][68];   // [k][row]
    __shared__ float Ks[DK][68];   // [k][col]
    int t = threadIdx.x, tx = t & 15, ty = t >> 4;
    int r0 = tr*64, c0 = tc*64;
    const float* Qb = g_Q + (size_t)b*NN*DK;
    const float* Kb = g_K + (size_t)b*NN*DK;
    #pragma unroll
    for (int i = 0; i < 16; i++) {
        int idx = t + i*256;            // 0..4095
        int r = idx >> 6, kk = idx & 63;
        Qs[kk][r] = Qb[(size_t)(r0+r)*DK + kk];
        Ks[kk][r] = Kb[(size_t)(c0+r)*DK + kk];
    }
    __syncthreads();
    float acc[4][4];
    #pragma unroll
    for (int i = 0; i < 4; i++)
        #pragma unroll
        for (int j = 0; j < 4; j++) acc[i][j] = 0.f;
    #pragma unroll
    for (int k = 0; k < DK; k++) {
        float4 xv = *reinterpret_cast<const float4*>(&Qs[k][ty*4]);
        float4 w4 = *reinterpret_cast<const float4*>(&Ks[k][tx*4]);
        float xr[4] = {xv.x, xv.y, xv.z, xv.w};
        float wr[4] = {w4.x, w4.y, w4.z, w4.w};
        #pragma unroll
        for (int i = 0; i < 4; i++)
            #pragma unroll
            for (int j = 0; j < 4; j++)
                acc[i][j] = fmaf(xr[i], wr[j], acc[i][j]);
    }
    float* Cb = g_compat + (size_t)b*NN*NN;
    #pragma unroll
    for (int i = 0; i < 4; i++) {
        int n = r0 + ty*4 + i;
        float4 o4 = make_float4(acc[i][0]*0.125f, acc[i][1]*0.125f,
                                acc[i][2]*0.125f, acc[i][3]*0.125f);
        *reinterpret_cast<float4*>(&Cb[(size_t)n*NN + c0 + tx*4]) = o4;
    }
}

// ============================================================
// Phase A (step t): per-row softmax stats of
// l_t(n,m) = compat(n,m) * (1 + step * cpack[n]·cpack[m])
// (cpack components >= t are zero, so the dot is exactly Σ_{s=1..t})
// ============================================================
__global__ void __launch_bounds__(256) kA_rowstat(const float* __restrict__ step_p) {
    __shared__ float lbuf[NN];
    __shared__ float red[8];
    int row = blockIdx.x;
    int b = row >> 11, n = row & (NN-1);
    float step = *step_p;
    float4 cn = g_cpack[row];
    const float* crow = g_compat + (size_t)b*NN*NN + (size_t)n*NN;
    const float4* packb = g_cpack + b*NN;

    float mx = -3.0e38f;
    for (int m = threadIdx.x; m <= n; m += 256) {
        float4 cm = packb[m];
        float dot = cn.x*cm.x + cn.y*cm.y + cn.z*cm.z + cn.w*cm.w;
        float l = crow[m] * fmaf(step, dot, 1.f);
        lbuf[m] = l;
        mx = fmaxf(mx, l);
    }
    int lane = threadIdx.x & 31, w = threadIdx.x >> 5;
    #pragma unroll
    for (int o = 16; o; o >>= 1) mx = fmaxf(mx, __shfl_xor_sync(0xffffffffu, mx, o));
    if (lane == 0) red[w] = mx;
    __syncthreads();
    mx = red[0];
    #pragma unroll
    for (int i = 1; i < 8; i++) mx = fmaxf(mx, red[i]);

    float zs = 0.f;
    for (int m = threadIdx.x; m <= n; m += 256) zs += __expf(lbuf[m] - mx);
    #pragma unroll
    for (int o = 16; o; o >>= 1) zs += __shfl_xor_sync(0xffffffffu, zs, o);
    __syncthreads();
    if (lane == 0) red[w] = zs;
    __syncthreads();
    if (threadIdx.x == 0) {
        float z = red[0];
        #pragma unroll
        for (int i = 1; i < 8; i++) z += red[i];
        g_M[row] = mx;
        g_Zinv[row] = 1.f / z;
    }
}

// ============================================================
// Phase B (step t): received[m] = Σ_n exp(l-M[n])·Zinv[n];
// c_{t+1} = c_t·(1 - decay·sigmoid(recv-1)); writes g_ccur and
// sets component t of g_cpack. Column-tiled, no atomics.
// ============================================================
__global__ void __launch_bounds__(256) kB_colsum(int t, const float* __restrict__ step_p,
                                                 const float* __restrict__ decay_p) {
    int b = blockIdx.y;
    int m0 = blockIdx.x * 64;
    int tid = threadIdx.x;
    int c = tid & 63, rg = tid >> 6;
    int m = m0 + c;
    float step = *step_p;
    float4 cm = g_cpack[b*NN + m];
    const float4* packb = g_cpack + b*NN;
    const float* Cb = g_compat + (size_t)b*NN*NN;

    float acc = 0.f;
    for (int n = m0 + rg; n < NN; n += 4) {
        if (n < m) continue;                 // only affects first 64 rows of tile
        float4 cnv = packb[n];
        float dot = cm.x*cnv.x + cm.y*cnv.y + cm.z*cnv.z + cm.w*cnv.w;
        float l = Cb[(size_t)n*NN + m] * fmaf(step, dot, 1.f);
        acc = fmaf(__expf(l - g_M[b*NN + n]), g_Zinv[b*NN + n], acc);
    }
    __shared__ float part[4][64];
    part[rg][c] = acc;
    __syncthreads();
    if (tid < 64) {
        float r = part[0][c] + part[1][c] + part[2][c] + part[3][c];
        float decay = *decay_p;
        float cprev = g_ccur[b*NN + m];
        float sig = 1.f / (1.f + __expf(-(r - 1.f)));
        float cnew = cprev * (1.f - decay*sig);
        g_ccur[b*NN + m] = cnew;
        float4 p = cm;
        if      (t == 0) p.x = cnew;
        else if (t == 1) p.y = cnew;
        else if (t == 2) p.z = cnew;
        else             p.w = cnew;
        g_cpack[b*NN + m] = p;
    }
}

// ============================================================
// K5: final softmax (l_4) fused with attn@V, flash-style tiles.
// Block: 256 thr, 64 query rows, iterate 64-col tiles <= row tile.
// ============================================================
__global__ void __launch_bounds__(256) k5_attnV(const float* __restrict__ step_p) {
    __shared__ float Cs[64][68];
    __shared__ float Vs[64][68];
    __shared__ float4 ccol[64];
    int b = blockIdx.y;
    int tr = blockIdx.x;
    int r0 = tr * 64;
    int t = threadIdx.x, tx = t & 15, ty = t >> 4;
    float step = *step_p;

    float4 crow[4];
    #pragma unroll
    for (int i = 0; i < 4; i++) crow[i] = g_cpack[b*NN + r0 + ty*4 + i];

    float acc[4][4];
    #pragma unroll
    for (int i = 0; i < 4; i++)
        #pragma unroll
        for (int j = 0; j < 4; j++) acc[i][j] = 0.f;
    float mrun[4], zrun[4];
    #pragma unroll
    for (int i = 0; i < 4; i++) { mrun[i] = -3.0e38f; zrun[i] = 0.f; }

    const float* Cb = g_compat + (size_t)b*NN*NN;
    const float* Vb = g_V + (size_t)b*NN*DK;

    for (int mt = 0; mt <= tr; mt++) {
        int m0 = mt * 64;
        #pragma unroll
        for (int i = 0; i < 16; i++) {
            int idx = t + i*256;
            int r = idx >> 6, c = idx & 63;
            Cs[r][c] = Cb[(size_t)(r0+r)*NN + m0 + c];
            Vs[r][c] = Vb[(size_t)(m0+r)*DK + c];
        }
        if (t < 64) ccol[t] = g_cpack[b*NN + m0 + t];
        __syncthreads();

        float l[4][4], tmax[4];
        #pragma unroll
        for (int i = 0; i < 4; i++) {
            int n = r0 + ty*4 + i;
            tmax[i] = -3.0e38f;
            #pragma unroll
            for (int j = 0; j < 4; j++) {
                int m = m0 + tx*4 + j;
                float4 cc = ccol[tx*4 + j];
                float dot = crow[i].x*cc.x + crow[i].y*cc.y + crow[i].z*cc.z + crow[i].w*cc.w;
                float lv = (m <= n) ? Cs[ty*4+i][tx*4+j] * fmaf(step, dot, 1.f) : -3.0e38f;
                l[i][j] = lv;
                tmax[i] = fmaxf(tmax[i], lv);
            }
        }
        #pragma unroll
        for (int i = 0; i < 4; i++) {
            #pragma unroll
            for (int o = 8; o; o >>= 1)
                tmax[i] = fmaxf(tmax[i], __shfl_xor_sync(0xffffffffu, tmax[i], o, 16));
        }
        float f[4], tsum[4];
        #pragma unroll
        for (int i = 0; i < 4; i++) {
            float nm = fmaxf(mrun[i], tmax[i]);
            f[i] = __expf(mrun[i] - nm);
            mrun[i] = nm;
            float s = 0.f;
            #pragma unroll
            for (int j = 0; j < 4; j++) {
                float e = __expf(l[i][j] - nm);
                l[i][j] = e;
                s += e;
            }
            tsum[i] = s;
        }
        #pragma unroll
        for (int i = 0; i < 4; i++) {
            #pragma unroll
            for (int o = 8; o; o >>= 1)
                tsum[i] += __shfl_xor_sync(0xffffffffu, tsum[i], o, 16);
            zrun[i] = zrun[i]*f[i] + tsum[i];
            #pragma unroll
            for (int j = 0; j < 4; j++) acc[i][j] *= f[i];
        }
        // write exp values back into Cs (each cell owned by this thread)
        #pragma unroll
        for (int i = 0; i < 4; i++)
            #pragma unroll
            for (int j = 0; j < 4; j++)
                Cs[ty*4+i][tx*4+j] = l[i][j];
        __syncthreads();
        // acc += E(64x64) @ Vtile(64x64)
        #pragma unroll 4
        for (int k = 0; k < 64; k += 4) {
            float4 e0 = *reinterpret_cast<const float4*>(&Cs[ty*4+0][k]);
            float4 e1 = *reinterpret_cast<const float4*>(&Cs[ty*4+1][k]);
            float4 e2 = *reinterpret_cast<const float4*>(&Cs[ty*4+2][k]);
            float4 e3 = *reinterpret_cast<const float4*>(&Cs[ty*4+3][k]);
            float er[4][4] = {{e0.x,e0.y,e0.z,e0.w},{e1.x,e1.y,e1.z,e1.w},
                              {e2.x,e2.y,e2.z,e2.w},{e3.x,e3.y,e3.z,e3.w}};
            #pragma unroll
            for (int q = 0; q < 4; q++) {
                float4 v = *reinterpret_cast<const float4*>(&Vs[k+q][tx*4]);
                float vr[4] = {v.x, v.y, v.z, v.w};
                #pragma unroll
                for (int i = 0; i < 4; i++)
                    #pragma unroll
                    for (int j = 0; j < 4; j++)
                        acc[i][j] = fmaf(er[i][q], vr[j], acc[i][j]);
            }
        }
        __syncthreads();
    }
    #pragma unroll
    for (int i = 0; i < 4; i++) {
        float zi = 1.f / zrun[i];
        int row = b*NN + r0 + ty*4 + i;
        float4 o4 = make_float4(acc[i][0]*zi, acc[i][1]*zi, acc[i][2]*zi, acc[i][3]*zi);
        *reinterpret_cast<float4*>(&g_AV[(size_t)row*DK + tx*4]) = o4;
    }
}

// ============================================================
// K6: out = alpha * (AV @ wo^T),  alpha = 0.2*sigmoid(mix_alpha)
// ============================================================
__global__ void __launch_bounds__(256) k6_out(const float* __restrict__ wo,
        const float* __restrict__ mix_p, float* __restrict__ out) {
    __shared__ float As[DK][68];   // [k][row]
    __shared__ float Ws[DK][68];   // [k][col]
    int t = threadIdx.x, tx = t & 15, ty = t >> 4;
    int r0 = blockIdx.y * 64, c0 = blockIdx.x * 64;
    #pragma unroll
    for (int i = 0; i < 16; i++) {
        int idx = t + i*256;
        int r = idx >> 6, kk = idx & 63;
        As[kk][r] = g_AV[(size_t)(r0+r)*DK + kk];
        Ws[kk][r] = wo[(size_t)(c0+r)*DK + kk];
    }
    __syncthreads();
    float acc[4][4];
    #pragma unroll
    for (int i = 0; i < 4; i++)
        #pragma unroll
        for (int j = 0; j < 4; j++) acc[i][j] = 0.f;
    #pragma unroll
    for (int k = 0; k < DK; k++) {
        float4 xv = *reinterpret_cast<const float4*>(&As[k][ty*4]);
        float4 w4 = *reinterpret_cast<const float4*>(&Ws[k][tx*4]);
        float xr[4] = {xv.x, xv.y, xv.z, xv.w};
        float wr[4] = {w4.x, w4.y, w4.z, w4.w};
        #pragma unroll
        for (int i = 0; i < 4; i++)
            #pragma unroll
            for (int j = 0; j < 4; j++)
                acc[i][j] = fmaf(xr[i], wr[j], acc[i][j]);
    }
    float alpha = 0.2f / (1.f + __expf(-mix_p[0]));
    #pragma unroll
    for (int i = 0; i < 4; i++) {
        int r = r0 + ty*4 + i;
        float4 o4 = make_float4(acc[i][0]*alpha, acc[i][1]*alpha,
                                acc[i][2]*alpha, acc[i][3]*alpha);
        *reinterpret_cast<float4*>(&out[(size_t)r*DD + c0 + tx*4]) = o4;
    }
}

// ============================================================
extern "C" void kernel_launch(void* const* d_in, const int* in_sizes, int n_in,
                              void* d_out, int out_size) {
    const float* X       = (const float*)d_in[0];
    // d_in[1] = attention_mask (all ones) — unused by the reference math
    const float* w1      = (const float*)d_in[2];
    const float* b1      = (const float*)d_in[3];
    const float* w2      = (const float*)d_in[4];
    const float* b2      = (const float*)d_in[5];
    const float* wq      = (const float*)d_in[6];
    const float* wk      = (const float*)d_in[7];
    const float* wc      = (const float*)d_in[8];
    const float* bc      = (const float*)d_in[9];
    const float* step_p  = (const float*)d_in[10];
    const float* decay_p = (const float*)d_in[11];
    const float* wv      = (const float*)d_in[12];
    const float* wo      = (const float*)d_in[13];
    const float* mix_p   = (const float*)d_in[14];
    float* out = (float*)d_out;

    k1_gemm<<<BN/64, 256>>>(X, w1, b1, wv);
    k2_feat<<<BN/8, 256>>>(w2, b2, wq, wk, wc, bc);
    k3_compat<<<dim3(NN/64, NN/64, BB), 256>>>();
    for (int t = 0; t < NSTEPS; t++) {
        kA_rowstat<<<BN, 256>>>(step_p);
        kB_colsum<<<dim3(NN/64, BB), 256>>>(t, step_p, decay_p);
    }
    k5_attnV<<<dim3(NN/64, BB), 256>>>(step_p);
    k6_out<<<dim3(DD/64, BN/64), 256>>>(wo, mix_p, out);
}

// round 5
// speedup vs baseline: 1.0711x; 1.0711x over previous
#include <cuda_runtime.h>
#include <math.h>

#define BB 8
#define NN 2048
#define DD 1024
#define H1 128
#define FF 28
#define DK 64
#define NSTEPS 4
#define BN (BB*NN)

// ---- scratch (static device globals; no runtime allocation) ----
static __device__ float  g_H[BN*H1];                  // gelu(X@W1^T+b1)
static __device__ float  g_V[BN*DK];                  // X@Wv^T
static __device__ float  g_Q[BN*DK];
static __device__ float  g_K[BN*DK];
static __device__ float  g_compat[(size_t)BB*NN*NN];  // 134 MB, lower triangle
static __device__ float  g_E[(size_t)BB*NN*NN];       // exp(logits), 134 MB
static __device__ float  g_ccur[BN];                  // current charge c_t
static __device__ float4 g_cpack[BN];                 // (c1,c2,c3,c4), zeroed per launch
static __device__ float  g_Zinv[BN];
static __device__ float  g_AV[BN*DK];                 // attn@V (normalized)

// ============================================================
// K1: fused GEMM Y[16384,192] = X @ [W1|Wv]^T, double-buffered,
// static smem (34 KB), K-tile = 16.
// ============================================================
__global__ void __launch_bounds__(256) k1_gemm(const float* __restrict__ X,
        const float* __restrict__ w1, const float* __restrict__ b1,
        const float* __restrict__ wv) {
    __shared__ float Xs[2][16][68];
    __shared__ float Ws[2][16][200];
    const int t  = threadIdx.x;
    const int tx = t & 15, ty = t >> 4;
    const int r0 = blockIdx.x * 64;

    float acc[4][12];
    #pragma unroll
    for (int i = 0; i < 4; i++)
        #pragma unroll
        for (int j = 0; j < 12; j++) acc[i][j] = 0.f;

    // preload tile 0
    #pragma unroll
    for (int i = 0; i < 4; i++) {
        int idx = t + i*256;  int r = idx >> 4, kk = idx & 15;
        Xs[0][kk][r] = X[(size_t)(r0+r)*DD + kk];
    }
    #pragma unroll
    for (int i = 0; i < 12; i++) {
        int idx = t + i*256;  int o = idx >> 4, kk = idx & 15;
        Ws[0][kk][o] = (o < H1) ? w1[o*DD + kk] : wv[(o-H1)*DD + kk];
    }
    __syncthreads();

    for (int kt = 0; kt < DD/16; kt++) {
        const int cur = kt & 1, nxt = cur ^ 1;
        float xr_st[4], wr_st[12];
        const bool more = (kt + 1 < DD/16);
        if (more) {
            int k0 = (kt+1)*16;
            #pragma unroll
            for (int i = 0; i < 4; i++) {
                int idx = t + i*256;  int r = idx >> 4, kk = idx & 15;
                xr_st[i] = X[(size_t)(r0+r)*DD + k0 + kk];
            }
            #pragma unroll
            for (int i = 0; i < 12; i++) {
                int idx = t + i*256;  int o = idx >> 4, kk = idx & 15;
                wr_st[i] = (o < H1) ? w1[o*DD + k0 + kk] : wv[(o-H1)*DD + k0 + kk];
            }
        }
        #pragma unroll
        for (int k = 0; k < 16; k++) {
            float4 xv = *reinterpret_cast<const float4*>(&Xs[cur][k][ty*4]);
            float xr[4] = {xv.x, xv.y, xv.z, xv.w};
            float wr[12];
            #pragma unroll
            for (int q = 0; q < 3; q++) {
                float4 w4 = *reinterpret_cast<const float4*>(&Ws[cur][k][tx*12 + q*4]);
                wr[q*4+0] = w4.x; wr[q*4+1] = w4.y; wr[q*4+2] = w4.z; wr[q*4+3] = w4.w;
            }
            #pragma unroll
            for (int i = 0; i < 4; i++)
                #pragma unroll
                for (int j = 0; j < 12; j++)
                    acc[i][j] = fmaf(xr[i], wr[j], acc[i][j]);
        }
        if (more) {
            #pragma unroll
            for (int i = 0; i < 4; i++) {
                int idx = t + i*256;  int r = idx >> 4, kk = idx & 15;
                Xs[nxt][kk][r] = xr_st[i];
            }
            #pragma unroll
            for (int i = 0; i < 12; i++) {
                int idx = t + i*256;  int o = idx >> 4, kk = idx & 15;
                Ws[nxt][kk][o] = wr_st[i];
            }
        }
        __syncthreads();
    }
    #pragma unroll
    for (int i = 0; i < 4; i++) {
        int r = r0 + ty*4 + i;
        #pragma unroll
        for (int j = 0; j < 12; j++) {
            int o = tx*12 + j;
            float v = acc[i][j];
            if (o < H1) {
                v += b1[o];
                v = 0.5f * v * (1.f + erff(v * 0.7071067811865476f));  // exact gelu
                g_H[(size_t)r*H1 + o] = v;
            } else {
                g_V[(size_t)r*DK + (o - H1)] = v;
            }
        }
    }
}

// ============================================================
// K2: features = sigmoid(H@W2^T+b2); Q/K; charge0; zero g_cpack
// ============================================================
__global__ void __launch_bounds__(256) k2_feat(const float* __restrict__ w2,
        const float* __restrict__ b2, const float* __restrict__ wq,
        const float* __restrict__ wk, const float* __restrict__ wc,
        const float* __restrict__ bc) {
    __shared__ float Hs[8][H1];
    __shared__ float Fs[8][FF];
    int warp = threadIdx.x >> 5, lane = threadIdx.x & 31;
    int row = blockIdx.x * 8 + warp;

    for (int k = lane; k < H1; k += 32) Hs[warp][k] = g_H[(size_t)row*H1 + k];
    __syncwarp();
    if (lane < FF) {
        float s = b2[lane];
        #pragma unroll 4
        for (int k = 0; k < H1; k++) s = fmaf(Hs[warp][k], w2[lane*H1 + k], s);
        Fs[warp][lane] = 1.f / (1.f + __expf(-s));
    }
    __syncwarp();
    #pragma unroll
    for (int half = 0; half < 2; half++) {
        int d = lane + half*32;
        float q = 0.f, kv = 0.f;
        #pragma unroll
        for (int j = 0; j < FF; j++) {
            float fv = Fs[warp][j];
            q  = fmaf(fv, wq[d*FF + j], q);
            kv = fmaf(fv, wk[d*FF + j], kv);
        }
        g_Q[(size_t)row*DK + d] = q;
        g_K[(size_t)row*DK + d] = kv;
    }
    if (lane == 0) {
        float s = bc[0];
        #pragma unroll
        for (int j = 0; j < FF; j++) s = fmaf(Fs[warp][j], wc[j], s);
        g_ccur[row] = 1.f / (1.f + __expf(-s));
        g_cpack[row] = make_float4(0.f, 0.f, 0.f, 0.f);   // per-launch reset (determinism)
    }
}

// ============================================================
// K3: compat[b,n,m] = Q[b,n]·K[b,m] / 8, lower-triangle tiles only
// ============================================================
__global__ void __launch_bounds__(256) k3_compat() {
    int tc = blockIdx.x, tr = blockIdx.y, b = blockIdx.z;
    if (tc > tr) return;
    __shared__ float Qs[DK][68];
    __shared__ float Ks[DK][68];
    int t = threadIdx.x, tx = t & 15, ty = t >> 4;
    int r0 = tr*64, c0 = tc*64;
    const float* Qb = g_Q + (size_t)b*NN*DK;
    const float* Kb = g_K + (size_t)b*NN*DK;
    #pragma unroll
    for (int i = 0; i < 16; i++) {
        int idx = t + i*256;
        int r = idx >> 6, kk = idx & 63;
        Qs[kk][r] = Qb[(size_t)(r0+r)*DK + kk];
        Ks[kk][r] = Kb[(size_t)(c0+r)*DK + kk];
    }
    __syncthreads();
    float acc[4][4];
    #pragma unroll
    for (int i = 0; i < 4; i++)
        #pragma unroll
        for (int j = 0; j < 4; j++) acc[i][j] = 0.f;
    #pragma unroll
    for (int k = 0; k < DK; k++) {
        float4 xv = *reinterpret_cast<const float4*>(&Qs[k][ty*4]);
        float4 w4 = *reinterpret_cast<const float4*>(&Ks[k][tx*4]);
        float xr[4] = {xv.x, xv.y, xv.z, xv.w};
        float wr[4] = {w4.x, w4.y, w4.z, w4.w};
        #pragma unroll
        for (int i = 0; i < 4; i++)
            #pragma unroll
            for (int j = 0; j < 4; j++)
                acc[i][j] = fmaf(xr[i], wr[j], acc[i][j]);
    }
    float* Cb = g_compat + (size_t)b*NN*NN;
    #pragma unroll
    for (int i = 0; i < 4; i++) {
        int n = r0 + ty*4 + i;
        float4 o4 = make_float4(acc[i][0]*0.125f, acc[i][1]*0.125f,
                                acc[i][2]*0.125f, acc[i][3]*0.125f);
        *reinterpret_cast<float4*>(&Cb[(size_t)n*NN + c0 + tx*4]) = o4;
    }
}

// ============================================================
// kA: single pass. l = compat*(1+step*cpack[n]·cpack[m]);
// E = exp(l) (0 beyond diagonal in last float4); Zinv[n] = 1/Σ E.
// No max subtraction: |l| <= ~6, fp32-safe.
// ============================================================
__global__ void __launch_bounds__(256) kA_expZ(const float* __restrict__ step_p) {
    __shared__ float red[8];
    int row = blockIdx.x;
    int b = row >> 11, n = row & (NN-1);
    float step = *step_p;
    float4 cn = g_cpack[row];
    const float4* crow4 = reinterpret_cast<const float4*>(g_compat + (size_t)b*NN*NN + (size_t)n*NN);
    float4*       erow4 = reinterpret_cast<float4*>(g_E + (size_t)b*NN*NN + (size_t)n*NN);
    const float4* packb = g_cpack + b*NN;
    int nblk = (n >> 2) + 1;

    float z = 0.f;
    for (int idx = threadIdx.x; idx < nblk; idx += 256) {
        float4 c4 = crow4[idx];
        int m0 = idx << 2;
        float4 p0 = packb[m0+0], p1 = packb[m0+1], p2 = packb[m0+2], p3 = packb[m0+3];
        float d0 = cn.x*p0.x + cn.y*p0.y + cn.z*p0.z + cn.w*p0.w;
        float d1 = cn.x*p1.x + cn.y*p1.y + cn.z*p1.z + cn.w*p1.w;
        float d2 = cn.x*p2.x + cn.y*p2.y + cn.z*p2.z + cn.w*p2.w;
        float d3 = cn.x*p3.x + cn.y*p3.y + cn.z*p3.z + cn.w*p3.w;
        float e0 = __expf(c4.x * fmaf(step, d0, 1.f));
        float e1 = __expf(c4.y * fmaf(step, d1, 1.f));
        float e2 = __expf(c4.z * fmaf(step, d2, 1.f));
        float e3 = __expf(c4.w * fmaf(step, d3, 1.f));
        if (m0 + 3 > n) {            // tail float4 of the row: zero beyond diagonal
            if (m0+1 > n) e1 = 0.f;
            if (m0+2 > n) e2 = 0.f;
            if (m0+3 > n) e3 = 0.f;
        }
        erow4[idx] = make_float4(e0, e1, e2, e3);
        z += (e0 + e1) + (e2 + e3);
    }
    int lane = threadIdx.x & 31, w = threadIdx.x >> 5;
    #pragma unroll
    for (int o = 16; o; o >>= 1) z += __shfl_xor_sync(0xffffffffu, z, o);
    if (lane == 0) red[w] = z;
    __syncthreads();
    if (threadIdx.x == 0) {
        float zt = red[0];
        #pragma unroll
        for (int i = 1; i < 8; i++) zt += red[i];
        g_Zinv[row] = 1.f / zt;
    }
}

// ============================================================
// kB (step t): recv[m] = Σ_{n>=m} E[n,m]*Zinv[n]  (pure mat-vec);
// c_{t+1} = c_t*(1 - decay*sigmoid(recv-1)); writes pack comp t.
// ============================================================
__global__ void __launch_bounds__(256) kB_recv(int t, const float* __restrict__ decay_p) {
    int b = blockIdx.y;
    int m0 = blockIdx.x * 64;
    int tid = threadIdx.x;
    int c = tid & 63, rg = tid >> 6;
    int m = m0 + c;
    const float* Eb = g_E + (size_t)b*NN*NN;
    const float* Zb = g_Zinv + b*NN;

    float acc = 0.f;
    // diagonal 64-row block (needs m<=n check)
    for (int n = m0 + rg; n < m0 + 64; n += 4)
        if (n >= m) acc = fmaf(Eb[(size_t)n*NN + m], Zb[n], acc);
    // remaining rows, unconditional
    #pragma unroll 4
    for (int n = m0 + 64 + rg; n < NN; n += 4)
        acc = fmaf(Eb[(size_t)n*NN + m], Zb[n], acc);

    __shared__ float part[4][64];
    part[rg][c] = acc;
    __syncthreads();
    if (tid < 64) {
        float r = part[0][c] + part[1][c] + part[2][c] + part[3][c];
        float decay = *decay_p;
        float cprev = g_ccur[b*NN + m];
        float sig = 1.f / (1.f + __expf(-(r - 1.f)));
        float cnew = cprev * (1.f - decay*sig);
        g_ccur[b*NN + m] = cnew;
        float4 p = g_cpack[b*NN + m];
        if      (t == 0) p.x = cnew;
        else if (t == 1) p.y = cnew;
        else if (t == 2) p.z = cnew;
        else             p.w = cnew;
        g_cpack[b*NN + m] = p;
    }
}

// ============================================================
// K5: AV[n] = Zinv[n] * Σ_m E[n,m]*V[m]  — pure tiled triangle GEMM
// ============================================================
__global__ void __launch_bounds__(256) k5_EV() {
    __shared__ float Es[64][68];
    __shared__ float Vs[64][68];
    int b = blockIdx.y;
    int tr = blockIdx.x;
    int r0 = tr * 64;
    int t = threadIdx.x, tx = t & 15, ty = t >> 4;

    float acc[4][4];
    #pragma unroll
    for (int i = 0; i < 4; i++)
        #pragma unroll
        for (int j = 0; j < 4; j++) acc[i][j] = 0.f;

    const float* Eb = g_E + (size_t)b*NN*NN;
    const float* Vb = g_V + (size_t)b*NN*DK;

    for (int mt = 0; mt <= tr; mt++) {
        int m0 = mt * 64;
        bool diag = (mt == tr);
        #pragma unroll
        for (int i = 0; i < 16; i++) {
            int idx = t + i*256;
            int r = idx >> 6, c = idx & 63;
            float ev = Eb[(size_t)(r0+r)*NN + m0 + c];
            if (diag && c > r) ev = 0.f;     // upper triangle of diagonal tile undefined
            Es[r][c] = ev;
            Vs[r][c] = Vb[(size_t)(m0+r)*DK + c];
        }
        __syncthreads();
        #pragma unroll 4
        for (int k = 0; k < 64; k += 4) {
            float4 e0 = *reinterpret_cast<const float4*>(&Es[ty*4+0][k]);
            float4 e1 = *reinterpret_cast<const float4*>(&Es[ty*4+1][k]);
            float4 e2 = *reinterpret_cast<const float4*>(&Es[ty*4+2][k]);
            float4 e3 = *reinterpret_cast<const float4*>(&Es[ty*4+3][k]);
            float er[4][4] = {{e0.x,e0.y,e0.z,e0.w},{e1.x,e1.y,e1.z,e1.w},
                              {e2.x,e2.y,e2.z,e2.w},{e3.x,e3.y,e3.z,e3.w}};
            #pragma unroll
            for (int q = 0; q < 4; q++) {
                float4 v = *reinterpret_cast<const float4*>(&Vs[k+q][tx*4]);
                float vr[4] = {v.x, v.y, v.z, v.w};
                #pragma unroll
                for (int i = 0; i < 4; i++)
                    #pragma unroll
                    for (int j = 0; j < 4; j++)
                        acc[i][j] = fmaf(er[i][q], vr[j], acc[i][j]);
            }
        }
        __syncthreads();
    }
    #pragma unroll
    for (int i = 0; i < 4; i++) {
        int row = b*NN + r0 + ty*4 + i;
        float zi = g_Zinv[row];
        float4 o4 = make_float4(acc[i][0]*zi, acc[i][1]*zi, acc[i][2]*zi, acc[i][3]*zi);
        *reinterpret_cast<float4*>(&g_AV[(size_t)row*DK + tx*4]) = o4;
    }
}

// ============================================================
// K6: out = alpha * (AV @ wo^T),  alpha = 0.2*sigmoid(mix_alpha)
// ============================================================
__global__ void __launch_bounds__(256) k6_out(const float* __restrict__ wo,
        const float* __restrict__ mix_p, float* __restrict__ out) {
    __shared__ float As[DK][68];
    __shared__ float Ws[DK][68];
    int t = threadIdx.x, tx = t & 15, ty = t >> 4;
    int r0 = blockIdx.y * 64, c0 = blockIdx.x * 64;
    #pragma unroll
    for (int i = 0; i < 16; i++) {
        int idx = t + i*256;
        int r = idx >> 6, kk = idx & 63;
        As[kk][r] = g_AV[(size_t)(r0+r)*DK + kk];
        Ws[kk][r] = wo[(size_t)(c0+r)*DK + kk];
    }
    __syncthreads();
    float acc[4][4];
    #pragma unroll
    for (int i = 0; i < 4; i++)
        #pragma unroll
        for (int j = 0; j < 4; j++) acc[i][j] = 0.f;
    #pragma unroll
    for (int k = 0; k < DK; k++) {
        float4 xv = *reinterpret_cast<const float4*>(&As[k][ty*4]);
        float4 w4 = *reinterpret_cast<const float4*>(&Ws[k][tx*4]);
        float xr[4] = {xv.x, xv.y, xv.z, xv.w};
        float wr[4] = {w4.x, w4.y, w4.z, w4.w};
        #pragma unroll
        for (int i = 0; i < 4; i++)
            #pragma unroll
            for (int j = 0; j < 4; j++)
                acc[i][j] = fmaf(xr[i], wr[j], acc[i][j]);
    }
    float alpha = 0.2f / (1.f + __expf(-mix_p[0]));
    #pragma unroll
    for (int i = 0; i < 4; i++) {
        int r = r0 + ty*4 + i;
        float4 o4 = make_float4(acc[i][0]*alpha, acc[i][1]*alpha,
                                acc[i][2]*alpha, acc[i][3]*alpha);
        *reinterpret_cast<float4*>(&out[(size_t)r*DD + c0 + tx*4]) = o4;
    }
}

// ============================================================
extern "C" void kernel_launch(void* const* d_in, const int* in_sizes, int n_in,
                              void* d_out, int out_size) {
    const float* X       = (const float*)d_in[0];
    // d_in[1] = attention_mask (all ones) — unused by the reference math
    const float* w1      = (const float*)d_in[2];
    const float* b1      = (const float*)d_in[3];
    const float* w2      = (const float*)d_in[4];
    const float* b2      = (const float*)d_in[5];
    const float* wq      = (const float*)d_in[6];
    const float* wk      = (const float*)d_in[7];
    const float* wc      = (const float*)d_in[8];
    const float* bc      = (const float*)d_in[9];
    const float* step_p  = (const float*)d_in[10];
    const float* decay_p = (const float*)d_in[11];
    const float* wv      = (const float*)d_in[12];
    const float* wo      = (const float*)d_in[13];
    const float* mix_p   = (const float*)d_in[14];
    float* out = (float*)d_out;

    k1_gemm<<<BN/64, 256>>>(X, w1, b1, wv);
    k2_feat<<<BN/8, 256>>>(w2, b2, wq, wk, wc, bc);
    k3_compat<<<dim3(NN/64, NN/64, BB), 256>>>();
    for (int t = 0; t < NSTEPS; t++) {
        kA_expZ<<<BN, 256>>>(step_p);
        kB_recv<<<dim3(NN/64, BB), 256>>>(t, decay_p);
    }
    kA_expZ<<<BN, 256>>>(step_p);     // 5th pass: E/Zinv for final attention
    k5_EV<<<dim3(NN/64, BB), 256>>>();
    k6_out<<<dim3(DD/64, BN/64), 256>>>(wo, mix_p, out);
}

// round 7
// speedup vs baseline: 1.2168x; 1.1360x over previous
#include <cuda_runtime.h>
#include <math.h>

#define BB 8
#define NN 2048
#define DD 1024
#define H1 128
#define FF 28
#define DK 64
#define NSTEPS 4
#define BN (BB*NN)

// ---- scratch (static device globals; no runtime allocation) ----
static __device__ float  g_H[BN*H1];
static __device__ float  g_V[BN*DK];
static __device__ float  g_Q[BN*DK];
static __device__ float  g_K[BN*DK];
static __device__ float  g_compat[(size_t)BB*NN*NN];  // lower triangle valid
static __device__ float  g_E[(size_t)BB*NN*NN];       // exp(logits)
static __device__ float  g_ccur[BN];
static __device__ float4 g_cpack[BN];                 // (c1,c2,c3,c4)
static __device__ float  g_Zinv[BN];
static __device__ float  g_AV[BN*DK];

// ============================================================
// K1: Y[16384,192] = X @ [W1|Wv]^T. 128x192 tile, 8x12 acc,
// double-buffered K-tile=16. 128 blocks (one wave).
// ============================================================
__global__ void __launch_bounds__(256) k1_gemm(const float* __restrict__ X,
        const float* __restrict__ w1, const float* __restrict__ b1,
        const float* __restrict__ wv) {
    __shared__ float Xs[2][16][132];
    __shared__ float Ws[2][16][200];
    const int t  = threadIdx.x;
    const int tx = t & 15, ty = t >> 4;
    const int r0 = blockIdx.x * 128;

    float acc[8][12];
    #pragma unroll
    for (int i = 0; i < 8; i++)
        #pragma unroll
        for (int j = 0; j < 12; j++) acc[i][j] = 0.f;

    // preload tile 0
    #pragma unroll
    for (int i = 0; i < 8; i++) {
        int idx = t + i*256;  int r = idx >> 4, kk = idx & 15;
        Xs[0][kk][r] = X[(size_t)(r0+r)*DD + kk];
    }
    #pragma unroll
    for (int i = 0; i < 12; i++) {
        int idx = t + i*256;  int o = idx >> 4, kk = idx & 15;
        Ws[0][kk][o] = (o < H1) ? w1[o*DD + kk] : wv[(o-H1)*DD + kk];
    }
    __syncthreads();

    for (int kt = 0; kt < DD/16; kt++) {
        const int cur = kt & 1, nxt = cur ^ 1;
        float xr_st[8], wr_st[12];
        const bool more = (kt + 1 < DD/16);
        if (more) {
            int k0 = (kt+1)*16;
            #pragma unroll
            for (int i = 0; i < 8; i++) {
                int idx = t + i*256;  int r = idx >> 4, kk = idx & 15;
                xr_st[i] = X[(size_t)(r0+r)*DD + k0 + kk];
            }
            #pragma unroll
            for (int i = 0; i < 12; i++) {
                int idx = t + i*256;  int o = idx >> 4, kk = idx & 15;
                wr_st[i] = (o < H1) ? w1[o*DD + k0 + kk] : wv[(o-H1)*DD + k0 + kk];
            }
        }
        #pragma unroll
        for (int k = 0; k < 16; k++) {
            float4 xa = *reinterpret_cast<const float4*>(&Xs[cur][k][ty*4]);
            float4 xb = *reinterpret_cast<const float4*>(&Xs[cur][k][64 + ty*4]);
            float xr[8] = {xa.x,xa.y,xa.z,xa.w, xb.x,xb.y,xb.z,xb.w};
            float4 w0 = *reinterpret_cast<const float4*>(&Ws[cur][k][tx*4]);
            float4 w1v = *reinterpret_cast<const float4*>(&Ws[cur][k][64 + tx*4]);
            float4 w2v = *reinterpret_cast<const float4*>(&Ws[cur][k][128 + tx*4]);
            float wr[12] = {w0.x,w0.y,w0.z,w0.w, w1v.x,w1v.y,w1v.z,w1v.w,
                            w2v.x,w2v.y,w2v.z,w2v.w};
            #pragma unroll
            for (int i = 0; i < 8; i++)
                #pragma unroll
                for (int j = 0; j < 12; j++)
                    acc[i][j] = fmaf(xr[i], wr[j], acc[i][j]);
        }
        if (more) {
            #pragma unroll
            for (int i = 0; i < 8; i++) {
                int idx = t + i*256;  int r = idx >> 4, kk = idx & 15;
                Xs[nxt][kk][r] = xr_st[i];
            }
            #pragma unroll
            for (int i = 0; i < 12; i++) {
                int idx = t + i*256;  int o = idx >> 4, kk = idx & 15;
                Ws[nxt][kk][o] = wr_st[i];
            }
        }
        __syncthreads();
    }
    // epilogue: cols {tx*4, 64+tx*4} -> H(gelu+b1); {128+tx*4} -> V
    float4 b1a = *reinterpret_cast<const float4*>(&b1[tx*4]);
    float4 b1b = *reinterpret_cast<const float4*>(&b1[64 + tx*4]);
    float ba[8] = {b1a.x,b1a.y,b1a.z,b1a.w, b1b.x,b1b.y,b1b.z,b1b.w};
    #pragma unroll
    for (int i = 0; i < 8; i++) {
        int r = r0 + (i < 4 ? ty*4 + i : 64 + ty*4 + (i-4));
        float h[8];
        #pragma unroll
        for (int j = 0; j < 8; j++) {
            float v = acc[i][j] + ba[j];
            h[j] = 0.5f * v * (1.f + erff(v * 0.7071067811865476f));
        }
        *reinterpret_cast<float4*>(&g_H[(size_t)r*H1 + tx*4])      = make_float4(h[0],h[1],h[2],h[3]);
        *reinterpret_cast<float4*>(&g_H[(size_t)r*H1 + 64 + tx*4]) = make_float4(h[4],h[5],h[6],h[7]);
        *reinterpret_cast<float4*>(&g_V[(size_t)r*DK + tx*4]) =
            make_float4(acc[i][8], acc[i][9], acc[i][10], acc[i][11]);
    }
}

// ============================================================
// K2: features = sigmoid(H@W2^T+b2); Q/K; charge0; zero g_cpack
// ============================================================
__global__ void __launch_bounds__(256) k2_feat(const float* __restrict__ w2,
        const float* __restrict__ b2, const float* __restrict__ wq,
        const float* __restrict__ wk, const float* __restrict__ wc,
        const float* __restrict__ bc) {
    __shared__ float Hs[8][H1];
    __shared__ float Fs[8][FF];
    int warp = threadIdx.x >> 5, lane = threadIdx.x & 31;
    int row = blockIdx.x * 8 + warp;

    for (int k = lane; k < H1; k += 32) Hs[warp][k] = g_H[(size_t)row*H1 + k];
    __syncwarp();
    if (lane < FF) {
        float s = b2[lane];
        #pragma unroll 4
        for (int k = 0; k < H1; k++) s = fmaf(Hs[warp][k], w2[lane*H1 + k], s);
        Fs[warp][lane] = 1.f / (1.f + __expf(-s));
    }
    __syncwarp();
    #pragma unroll
    for (int half = 0; half < 2; half++) {
        int d = lane + half*32;
        float q = 0.f, kv = 0.f;
        #pragma unroll
        for (int j = 0; j < FF; j++) {
            float fv = Fs[warp][j];
            q  = fmaf(fv, wq[d*FF + j], q);
            kv = fmaf(fv, wk[d*FF + j], kv);
        }
        g_Q[(size_t)row*DK + d] = q;
        g_K[(size_t)row*DK + d] = kv;
    }
    if (lane == 0) {
        float s = bc[0];
        #pragma unroll
        for (int j = 0; j < FF; j++) s = fmaf(Fs[warp][j], wc[j], s);
        g_ccur[row] = 1.f / (1.f + __expf(-s));
        g_cpack[row] = make_float4(0.f, 0.f, 0.f, 0.f);
    }
}

// ============================================================
// K3: compat = Q@K^T/8.  128x128 tiles (triangle), 8x8 acc,
// K-chunks of 32. smem 33.8 KB.
// ============================================================
__global__ void __launch_bounds__(256) k3_compat() {
    int tc = blockIdx.x, tr = blockIdx.y, b = blockIdx.z;
    if (tc > tr) return;
    __shared__ float Qs[32][132];
    __shared__ float Ks[32][132];
    int t = threadIdx.x, tx = t & 15, ty = t >> 4;
    int r0 = tr*128, c0 = tc*128;
    const float* Qb = g_Q + (size_t)b*NN*DK;
    const float* Kb = g_K + (size_t)b*NN*DK;

    float acc[8][8];
    #pragma unroll
    for (int i = 0; i < 8; i++)
        #pragma unroll
        for (int j = 0; j < 8; j++) acc[i][j] = 0.f;

    for (int kc = 0; kc < 2; kc++) {
        int kb0 = kc*32;
        #pragma unroll
        for (int i = 0; i < 16; i++) {
            int idx = t + i*256;            // 0..4095
            int r = idx >> 5, kk = idx & 31;
            Qs[kk][r] = Qb[(size_t)(r0+r)*DK + kb0 + kk];
            Ks[kk][r] = Kb[(size_t)(c0+r)*DK + kb0 + kk];
        }
        __syncthreads();
        #pragma unroll
        for (int k = 0; k < 32; k++) {
            float4 qa = *reinterpret_cast<const float4*>(&Qs[k][ty*4]);
            float4 qb = *reinterpret_cast<const float4*>(&Qs[k][64 + ty*4]);
            float4 ka = *reinterpret_cast<const float4*>(&Ks[k][tx*4]);
            float4 kb = *reinterpret_cast<const float4*>(&Ks[k][64 + tx*4]);
            float xr[8] = {qa.x,qa.y,qa.z,qa.w, qb.x,qb.y,qb.z,qb.w};
            float wr[8] = {ka.x,ka.y,ka.z,ka.w, kb.x,kb.y,kb.z,kb.w};
            #pragma unroll
            for (int i = 0; i < 8; i++)
                #pragma unroll
                for (int j = 0; j < 8; j++)
                    acc[i][j] = fmaf(xr[i], wr[j], acc[i][j]);
        }
        __syncthreads();
    }
    float* Cb = g_compat + (size_t)b*NN*NN;
    #pragma unroll
    for (int i = 0; i < 8; i++) {
        int n = r0 + (i < 4 ? ty*4 + i : 64 + ty*4 + (i-4));
        *reinterpret_cast<float4*>(&Cb[(size_t)n*NN + c0 + tx*4]) =
            make_float4(acc[i][0]*0.125f, acc[i][1]*0.125f, acc[i][2]*0.125f, acc[i][3]*0.125f);
        *reinterpret_cast<float4*>(&Cb[(size_t)n*NN + c0 + 64 + tx*4]) =
            make_float4(acc[i][4]*0.125f, acc[i][5]*0.125f, acc[i][6]*0.125f, acc[i][7]*0.125f);
    }
}

// ============================================================
// kA: E = exp(compat*(1+step*cpack[n]·cpack[m])), Zinv[n]=1/ΣE.
// Scalar-m per thread -> all loads/stores coalesced.
// ============================================================
__global__ void __launch_bounds__(256) kA_expZ(const float* __restrict__ step_p) {
    __shared__ float red[8];
    int row = blockIdx.x;
    int b = row >> 11, n = row & (NN-1);
    float step = *step_p;
    float4 cn = g_cpack[row];
    const float* crow = g_compat + (size_t)b*NN*NN + (size_t)n*NN;
    float*       erow = g_E + (size_t)b*NN*NN + (size_t)n*NN;
    const float4* packb = g_cpack + b*NN;

    float z = 0.f;
    for (int m = threadIdx.x; m <= n; m += 256) {
        float4 cm = packb[m];
        float dot = cn.x*cm.x + cn.y*cm.y + cn.z*cm.z + cn.w*cm.w;
        float e = __expf(crow[m] * fmaf(step, dot, 1.f));
        erow[m] = e;
        z += e;
    }
    int lane = threadIdx.x & 31, w = threadIdx.x >> 5;
    #pragma unroll
    for (int o = 16; o; o >>= 1) z += __shfl_xor_sync(0xffffffffu, z, o);
    if (lane == 0) red[w] = z;
    __syncthreads();
    if (threadIdx.x == 0) {
        float zt = red[0];
        #pragma unroll
        for (int i = 1; i < 8; i++) zt += red[i];
        g_Zinv[row] = 1.f / zt;
    }
}

// ============================================================
// kB (step t): recv[m] = Σ_{n>=m} E[n,m]*Zinv[n]; charge update.
// 512 threads, 8-way n split.
// ============================================================
__global__ void __launch_bounds__(512) kB_recv(int t, const float* __restrict__ decay_p) {
    int b = blockIdx.y;
    int m0 = blockIdx.x * 64;
    int tid = threadIdx.x;
    int c = tid & 63, rg = tid >> 6;       // rg 0..7
    int m = m0 + c;
    const float* Eb = g_E + (size_t)b*NN*NN;
    const float* Zb = g_Zinv + b*NN;

    float acc = 0.f;
    for (int n = m0 + rg; n < m0 + 64; n += 8)
        if (n >= m) acc = fmaf(Eb[(size_t)n*NN + m], Zb[n], acc);
    #pragma unroll 4
    for (int n = m0 + 64 + rg; n < NN; n += 8)
        acc = fmaf(Eb[(size_t)n*NN + m], Zb[n], acc);

    __shared__ float part[8][64];
    part[rg][c] = acc;
    __syncthreads();
    if (tid < 64) {
        float r = part[0][c] + part[1][c] + part[2][c] + part[3][c]
                + part[4][c] + part[5][c] + part[6][c] + part[7][c];
        float decay = *decay_p;
        float cprev = g_ccur[b*NN + m];
        float sig = 1.f / (1.f + __expf(-(r - 1.f)));
        float cnew = cprev * (1.f - decay*sig);
        g_ccur[b*NN + m] = cnew;
        float4 p = g_cpack[b*NN + m];
        if      (t == 0) p.x = cnew;
        else if (t == 1) p.y = cnew;
        else if (t == 2) p.z = cnew;
        else             p.w = cnew;
        g_cpack[b*NN + m] = p;
    }
}

// ============================================================
// K5: AV[n] = Zinv[n] * Σ_m E[n,m]*V[m]  — tiled triangle GEMM
// ============================================================
__global__ void __launch_bounds__(256) k5_EV() {
    __shared__ float Es[64][68];
    __shared__ float Vs[64][68];
    int b = blockIdx.y;
    int tr = blockIdx.x;
    int r0 = tr * 64;
    int t = threadIdx.x, tx = t & 15, ty = t >> 4;

    float acc[4][4];
    #pragma unroll
    for (int i = 0; i < 4; i++)
        #pragma unroll
        for (int j = 0; j < 4; j++) acc[i][j] = 0.f;

    const float* Eb = g_E + (size_t)b*NN*NN;
    const float* Vb = g_V + (size_t)b*NN*DK;

    for (int mt = 0; mt <= tr; mt++) {
        int m0 = mt * 64;
        bool diag = (mt == tr);
        #pragma unroll
        for (int i = 0; i < 16; i++) {
            int idx = t + i*256;
            int r = idx >> 6, c = idx & 63;
            float ev = Eb[(size_t)(r0+r)*NN + m0 + c];
            if (diag && c > r) ev = 0.f;
            Es[r][c] = ev;
            Vs[r][c] = Vb[(size_t)(m0+r)*DK + c];
        }
        __syncthreads();
        #pragma unroll 4
        for (int k = 0; k < 64; k += 4) {
            float4 e0 = *reinterpret_cast<const float4*>(&Es[ty*4+0][k]);
            float4 e1 = *reinterpret_cast<const float4*>(&Es[ty*4+1][k]);
            float4 e2 = *reinterpret_cast<const float4*>(&Es[ty*4+2][k]);
            float4 e3 = *reinterpret_cast<const float4*>(&Es[ty*4+3][k]);
            float er[4][4] = {{e0.x,e0.y,e0.z,e0.w},{e1.x,e1.y,e1.z,e1.w},
                              {e2.x,e2.y,e2.z,e2.w},{e3.x,e3.y,e3.z,e3.w}};
            #pragma unroll
            for (int q = 0; q < 4; q++) {
                float4 v = *reinterpret_cast<const float4*>(&Vs[k+q][tx*4]);
                float vr[4] = {v.x, v.y, v.z, v.w};
                #pragma unroll
                for (int i = 0; i < 4; i++)
                    #pragma unroll
                    for (int j = 0; j < 4; j++)
                        acc[i][j] = fmaf(er[i][q], vr[j], acc[i][j]);
            }
        }
        __syncthreads();
    }
    #pragma unroll
    for (int i = 0; i < 4; i++) {
        int row = b*NN + r0 + ty*4 + i;
        float zi = g_Zinv[row];
        *reinterpret_cast<float4*>(&g_AV[(size_t)row*DK + tx*4]) =
            make_float4(acc[i][0]*zi, acc[i][1]*zi, acc[i][2]*zi, acc[i][3]*zi);
    }
}

// ============================================================
// K6: out = alpha * (AV @ wo^T)
// ============================================================
__global__ void __launch_bounds__(256) k6_out(const float* __restrict__ wo,
        const float* __restrict__ mix_p, float* __restrict__ out) {
    __shared__ float As[DK][68];
    __shared__ float Ws[DK][68];
    int t = threadIdx.x, tx = t & 15, ty = t >> 4;
    int r0 = blockIdx.y * 64, c0 = blockIdx.x * 64;
    #pragma unroll
    for (int i = 0; i < 16; i++) {
        int idx = t + i*256;
        int r = idx >> 6, kk = idx & 63;
        As[kk][r] = g_AV[(size_t)(r0+r)*DK + kk];
        Ws[kk][r] = wo[(size_t)(c0+r)*DK + kk];
    }
    __syncthreads();
    float acc[4][4];
    #pragma unroll
    for (int i = 0; i < 4; i++)
        #pragma unroll
        for (int j = 0; j < 4; j++) acc[i][j] = 0.f;
    #pragma unroll
    for (int k = 0; k < DK; k++) {
        float4 xv = *reinterpret_cast<const float4*>(&As[k][ty*4]);
        float4 w4 = *reinterpret_cast<const float4*>(&Ws[k][tx*4]);
        float xr[4] = {xv.x, xv.y, xv.z, xv.w};
        float wr[4] = {w4.x, w4.y, w4.z, w4.w};
        #pragma unroll
        for (int i = 0; i < 4; i++)
            #pragma unroll
            for (int j = 0; j < 4; j++)
                acc[i][j] = fmaf(xr[i], wr[j], acc[i][j]);
    }
    float alpha = 0.2f / (1.f + __expf(-mix_p[0]));
    #pragma unroll
    for (int i = 0; i < 4; i++) {
        int r = r0 + ty*4 + i;
        *reinterpret_cast<float4*>(&out[(size_t)r*DD + c0 + tx*4]) =
            make_float4(acc[i][0]*alpha, acc[i][1]*alpha, acc[i][2]*alpha, acc[i][3]*alpha);
    }
}

// ============================================================
extern "C" void kernel_launch(void* const* d_in, const int* in_sizes, int n_in,
                              void* d_out, int out_size) {
    const float* X       = (const float*)d_in[0];
    const float* w1      = (const float*)d_in[2];
    const float* b1      = (const float*)d_in[3];
    const float* w2      = (const float*)d_in[4];
    const float* b2      = (const float*)d_in[5];
    const float* wq      = (const float*)d_in[6];
    const float* wk      = (const float*)d_in[7];
    const float* wc      = (const float*)d_in[8];
    const float* bc      = (const float*)d_in[9];
    const float* step_p  = (const float*)d_in[10];
    const float* decay_p = (const float*)d_in[11];
    const float* wv      = (const float*)d_in[12];
    const float* wo      = (const float*)d_in[13];
    const float* mix_p   = (const float*)d_in[14];
    float* out = (float*)d_out;

    k1_gemm<<<BN/128, 256>>>(X, w1, b1, wv);
    k2_feat<<<BN/8, 256>>>(w2, b2, wq, wk, wc, bc);
    k3_compat<<<dim3(NN/128, NN/128, BB), 256>>>();
    for (int t = 0; t < NSTEPS; t++) {
        kA_expZ<<<BN, 256>>>(step_p);
        kB_recv<<<dim3(NN/64, BB), 512>>>(t, decay_p);
    }
    kA_expZ<<<BN, 256>>>(step_p);     // 5th pass: E/Zinv for final attention
    k5_EV<<<dim3(NN/64, BB), 256>>>();
    k6_out<<<dim3(DD/64, BN/64), 256>>>(wo, mix_p, out);
}

// round 9
// speedup vs baseline: 1.3296x; 1.0927x over previous
#include <cuda_runtime.h>
#include <math.h>

#define BB 8
#define NN 2048
#define DD 1024
#define H1 128
#define FF 28
#define DK 64
#define NSTEPS 4
#define BN (BB*NN)

// ---- scratch (static device globals; no runtime allocation) ----
static __device__ float  g_H[BN*H1];
static __device__ float  g_V[BN*DK];
static __device__ float  g_Q[BN*DK];
static __device__ float  g_K[BN*DK];
static __device__ float  g_compat[(size_t)BB*NN*NN];  // lower triangle valid
static __device__ float  g_ccur[BN];
static __device__ float4 g_cpack[BN];                 // (c1,c2,c3,c4)
static __device__ float  g_Zinv[BN];
static __device__ float  g_AV[BN*DK];

// ============================================================
// K1: Y[16384,192] = X @ [W1|Wv]^T. 128x192 tile, 8x12 acc,
// double-buffered K-tile=16. 128 blocks (one wave).
// ============================================================
__global__ void __launch_bounds__(256) k1_gemm(const float* __restrict__ X,
        const float* __restrict__ w1, const float* __restrict__ b1,
        const float* __restrict__ wv) {
    __shared__ float Xs[2][16][132];
    __shared__ float Ws[2][16][200];
    const int t  = threadIdx.x;
    const int tx = t & 15, ty = t >> 4;
    const int r0 = blockIdx.x * 128;

    float acc[8][12];
    #pragma unroll
    for (int i = 0; i < 8; i++)
        #pragma unroll
        for (int j = 0; j < 12; j++) acc[i][j] = 0.f;

    #pragma unroll
    for (int i = 0; i < 8; i++) {
        int idx = t + i*256;  int r = idx >> 4, kk = idx & 15;
        Xs[0][kk][r] = X[(size_t)(r0+r)*DD + kk];
    }
    #pragma unroll
    for (int i = 0; i < 12; i++) {
        int idx = t + i*256;  int o = idx >> 4, kk = idx & 15;
        Ws[0][kk][o] = (o < H1) ? w1[o*DD + kk] : wv[(o-H1)*DD + kk];
    }
    __syncthreads();

    for (int kt = 0; kt < DD/16; kt++) {
        const int cur = kt & 1, nxt = cur ^ 1;
        float xr_st[8], wr_st[12];
        const bool more = (kt + 1 < DD/16);
        if (more) {
            int k0 = (kt+1)*16;
            #pragma unroll
            for (int i = 0; i < 8; i++) {
                int idx = t + i*256;  int r = idx >> 4, kk = idx & 15;
                xr_st[i] = X[(size_t)(r0+r)*DD + k0 + kk];
            }
            #pragma unroll
            for (int i = 0; i < 12; i++) {
                int idx = t + i*256;  int o = idx >> 4, kk = idx & 15;
                wr_st[i] = (o < H1) ? w1[o*DD + k0 + kk] : wv[(o-H1)*DD + k0 + kk];
            }
        }
        #pragma unroll
        for (int k = 0; k < 16; k++) {
            float4 xa = *reinterpret_cast<const float4*>(&Xs[cur][k][ty*4]);
            float4 xb = *reinterpret_cast<const float4*>(&Xs[cur][k][64 + ty*4]);
            float xr[8] = {xa.x,xa.y,xa.z,xa.w, xb.x,xb.y,xb.z,xb.w};
            float4 w0 = *reinterpret_cast<const float4*>(&Ws[cur][k][tx*4]);
            float4 w1v = *reinterpret_cast<const float4*>(&Ws[cur][k][64 + tx*4]);
            float4 w2v = *reinterpret_cast<const float4*>(&Ws[cur][k][128 + tx*4]);
            float wr[12] = {w0.x,w0.y,w0.z,w0.w, w1v.x,w1v.y,w1v.z,w1v.w,
                            w2v.x,w2v.y,w2v.z,w2v.w};
            #pragma unroll
            for (int i = 0; i < 8; i++)
                #pragma unroll
                for (int j = 0; j < 12; j++)
                    acc[i][j] = fmaf(xr[i], wr[j], acc[i][j]);
        }
        if (more) {
            #pragma unroll
            for (int i = 0; i < 8; i++) {
                int idx = t + i*256;  int r = idx >> 4, kk = idx & 15;
                Xs[nxt][kk][r] = xr_st[i];
            }
            #pragma unroll
            for (int i = 0; i < 12; i++) {
                int idx = t + i*256;  int o = idx >> 4, kk = idx & 15;
                Ws[nxt][kk][o] = wr_st[i];
            }
        }
        __syncthreads();
    }
    float4 b1a = *reinterpret_cast<const float4*>(&b1[tx*4]);
    float4 b1b = *reinterpret_cast<const float4*>(&b1[64 + tx*4]);
    float ba[8] = {b1a.x,b1a.y,b1a.z,b1a.w, b1b.x,b1b.y,b1b.z,b1b.w};
    #pragma unroll
    for (int i = 0; i < 8; i++) {
        int r = r0 + (i < 4 ? ty*4 + i : 64 + ty*4 + (i-4));
        float h[8];
        #pragma unroll
        for (int j = 0; j < 8; j++) {
            float v = acc[i][j] + ba[j];
            h[j] = 0.5f * v * (1.f + erff(v * 0.7071067811865476f));
        }
        *reinterpret_cast<float4*>(&g_H[(size_t)r*H1 + tx*4])      = make_float4(h[0],h[1],h[2],h[3]);
        *reinterpret_cast<float4*>(&g_H[(size_t)r*H1 + 64 + tx*4]) = make_float4(h[4],h[5],h[6],h[7]);
        *reinterpret_cast<float4*>(&g_V[(size_t)r*DK + tx*4]) =
            make_float4(acc[i][8], acc[i][9], acc[i][10], acc[i][11]);
    }
}

// ============================================================
// K2: features = sigmoid(H@W2^T+b2); Q/K; charge0; zero g_cpack
// ============================================================
__global__ void __launch_bounds__(256) k2_feat(const float* __restrict__ w2,
        const float* __restrict__ b2, const float* __restrict__ wq,
        const float* __restrict__ wk, const float* __restrict__ wc,
        const float* __restrict__ bc) {
    __shared__ float Hs[8][H1];
    __shared__ float Fs[8][FF];
    int warp = threadIdx.x >> 5, lane = threadIdx.x & 31;
    int row = blockIdx.x * 8 + warp;

    for (int k = lane; k < H1; k += 32) Hs[warp][k] = g_H[(size_t)row*H1 + k];
    __syncwarp();
    if (lane < FF) {
        float s = b2[lane];
        #pragma unroll 4
        for (int k = 0; k < H1; k++) s = fmaf(Hs[warp][k], w2[lane*H1 + k], s);
        Fs[warp][lane] = 1.f / (1.f + __expf(-s));
    }
    __syncwarp();
    #pragma unroll
    for (int half = 0; half < 2; half++) {
        int d = lane + half*32;
        float q = 0.f, kv = 0.f;
        #pragma unroll
        for (int j = 0; j < FF; j++) {
            float fv = Fs[warp][j];
            q  = fmaf(fv, wq[d*FF + j], q);
            kv = fmaf(fv, wk[d*FF + j], kv);
        }
        g_Q[(size_t)row*DK + d] = q;
        g_K[(size_t)row*DK + d] = kv;
    }
    if (lane == 0) {
        float s = bc[0];
        #pragma unroll
        for (int j = 0; j < FF; j++) s = fmaf(Fs[warp][j], wc[j], s);
        g_ccur[row] = 1.f / (1.f + __expf(-s));
        g_cpack[row] = make_float4(0.f, 0.f, 0.f, 0.f);
    }
}

// ============================================================
// K3: compat = Q@K^T/8.  128x128 tiles (triangle), 8x8 acc.
// ============================================================
__global__ void __launch_bounds__(256) k3_compat() {
    int tc = blockIdx.x, tr = blockIdx.y, b = blockIdx.z;
    if (tc > tr) return;
    __shared__ float Qs[32][132];
    __shared__ float Ks[32][132];
    int t = threadIdx.x, tx = t & 15, ty = t >> 4;
    int r0 = tr*128, c0 = tc*128;
    const float* Qb = g_Q + (size_t)b*NN*DK;
    const float* Kb = g_K + (size_t)b*NN*DK;

    float acc[8][8];
    #pragma unroll
    for (int i = 0; i < 8; i++)
        #pragma unroll
        for (int j = 0; j < 8; j++) acc[i][j] = 0.f;

    for (int kc = 0; kc < 2; kc++) {
        int kb0 = kc*32;
        #pragma unroll
        for (int i = 0; i < 16; i++) {
            int idx = t + i*256;
            int r = idx >> 5, kk = idx & 31;
            Qs[kk][r] = Qb[(size_t)(r0+r)*DK + kb0 + kk];
            Ks[kk][r] = Kb[(size_t)(c0+r)*DK + kb0 + kk];
        }
        __syncthreads();
        #pragma unroll
        for (int k = 0; k < 32; k++) {
            float4 qa = *reinterpret_cast<const float4*>(&Qs[k][ty*4]);
            float4 qb = *reinterpret_cast<const float4*>(&Qs[k][64 + ty*4]);
            float4 ka = *reinterpret_cast<const float4*>(&Ks[k][tx*4]);
            float4 kb = *reinterpret_cast<const float4*>(&Ks[k][64 + tx*4]);
            float xr[8] = {qa.x,qa.y,qa.z,qa.w, qb.x,qb.y,qb.z,qb.w};
            float wr[8] = {ka.x,ka.y,ka.z,ka.w, kb.x,kb.y,kb.z,kb.w};
            #pragma unroll
            for (int i = 0; i < 8; i++)
                #pragma unroll
                for (int j = 0; j < 8; j++)
                    acc[i][j] = fmaf(xr[i], wr[j], acc[i][j]);
        }
        __syncthreads();
    }
    float* Cb = g_compat + (size_t)b*NN*NN;
    #pragma unroll
    for (int i = 0; i < 8; i++) {
        int n = r0 + (i < 4 ? ty*4 + i : 64 + ty*4 + (i-4));
        *reinterpret_cast<float4*>(&Cb[(size_t)n*NN + c0 + tx*4]) =
            make_float4(acc[i][0]*0.125f, acc[i][1]*0.125f, acc[i][2]*0.125f, acc[i][3]*0.125f);
        *reinterpret_cast<float4*>(&Cb[(size_t)n*NN + c0 + 64 + tx*4]) =
            make_float4(acc[i][4]*0.125f, acc[i][5]*0.125f, acc[i][6]*0.125f, acc[i][7]*0.125f);
    }
}

// ============================================================
// kA: Zinv[n] = 1/Σ_m exp(compat*(1+step*cpack[n]·cpack[m])).
// Read-only; manual 4x unroll for MLP.
// ============================================================
__global__ void __launch_bounds__(256) kA_Z(const float* __restrict__ step_p) {
    __shared__ float red[8];
    int row = blockIdx.x;
    int b = row >> 11, n = row & (NN-1);
    float step = *step_p;
    float4 cn = g_cpack[row];
    const float* crow = g_compat + (size_t)b*NN*NN + (size_t)n*NN;
    const float4* packb = g_cpack + b*NN;

    float z = 0.f;
    int m = threadIdx.x;
    for (; m + 768 <= n; m += 1024) {
        float  c0 = crow[m],     c1 = crow[m+256], c2 = crow[m+512], c3 = crow[m+768];
        float4 p0 = packb[m],    p1 = packb[m+256], p2 = packb[m+512], p3 = packb[m+768];
        float d0 = cn.x*p0.x + cn.y*p0.y + cn.z*p0.z + cn.w*p0.w;
        float d1 = cn.x*p1.x + cn.y*p1.y + cn.z*p1.z + cn.w*p1.w;
        float d2 = cn.x*p2.x + cn.y*p2.y + cn.z*p2.z + cn.w*p2.w;
        float d3 = cn.x*p3.x + cn.y*p3.y + cn.z*p3.z + cn.w*p3.w;
        float e0 = __expf(c0 * fmaf(step, d0, 1.f));
        float e1 = __expf(c1 * fmaf(step, d1, 1.f));
        float e2 = __expf(c2 * fmaf(step, d2, 1.f));
        float e3 = __expf(c3 * fmaf(step, d3, 1.f));
        z += (e0 + e1) + (e2 + e3);
    }
    for (; m <= n; m += 256) {
        float4 cm = packb[m];
        float dot = cn.x*cm.x + cn.y*cm.y + cn.z*cm.z + cn.w*cm.w;
        z += __expf(crow[m] * fmaf(step, dot, 1.f));
    }
    int lane = threadIdx.x & 31, w = threadIdx.x >> 5;
    #pragma unroll
    for (int o = 16; o; o >>= 1) z += __shfl_xor_sync(0xffffffffu, z, o);
    if (lane == 0) red[w] = z;
    __syncthreads();
    if (threadIdx.x == 0) {
        float zt = red[0];
        #pragma unroll
        for (int i = 1; i < 8; i++) zt += red[i];
        g_Zinv[row] = 1.f / zt;
    }
}

// ============================================================
// kB (step t): recv[m] = Σ_{n>=m} exp(l(n,m))·Zinv[n], exp
// recomputed from compat. 512 threads, 8-way n split, 4x unroll.
// ============================================================
__global__ void __launch_bounds__(512) kB_recv(int t, const float* __restrict__ step_p,
                                               const float* __restrict__ decay_p) {
    int b = blockIdx.y;
    int m0 = blockIdx.x * 64;
    int tid = threadIdx.x;
    int c = tid & 63, rg = tid >> 6;       // rg 0..7
    int m = m0 + c;
    float step = *step_p;
    float4 cm = g_cpack[b*NN + m];
    const float* Cb = g_compat + (size_t)b*NN*NN;
    const float* Zb = g_Zinv + b*NN;
    const float4* packb = g_cpack + b*NN;

    float acc = 0.f;
    // diagonal 64-row block (needs m<=n check)
    for (int n = m0 + rg; n < m0 + 64; n += 8) {
        if (n >= m) {
            float4 cn = packb[n];
            float dot = cm.x*cn.x + cm.y*cn.y + cm.z*cn.z + cm.w*cn.w;
            float e = __expf(Cb[(size_t)n*NN + m] * fmaf(step, dot, 1.f));
            acc = fmaf(e, Zb[n], acc);
        }
    }
    int n = m0 + 64 + rg;
    for (; n + 24 < NN; n += 32) {
        float  v0 = Cb[(size_t)(n   )*NN + m], v1 = Cb[(size_t)(n+ 8)*NN + m];
        float  v2 = Cb[(size_t)(n+16)*NN + m], v3 = Cb[(size_t)(n+24)*NN + m];
        float4 p0 = packb[n], p1 = packb[n+8], p2 = packb[n+16], p3 = packb[n+24];
        float z0 = Zb[n], z1 = Zb[n+8], z2 = Zb[n+16], z3 = Zb[n+24];
        float d0 = cm.x*p0.x + cm.y*p0.y + cm.z*p0.z + cm.w*p0.w;
        float d1 = cm.x*p1.x + cm.y*p1.y + cm.z*p1.z + cm.w*p1.w;
        float d2 = cm.x*p2.x + cm.y*p2.y + cm.z*p2.z + cm.w*p2.w;
        float d3 = cm.x*p3.x + cm.y*p3.y + cm.z*p3.z + cm.w*p3.w;
        acc = fmaf(__expf(v0 * fmaf(step, d0, 1.f)), z0, acc);
        acc = fmaf(__expf(v1 * fmaf(step, d1, 1.f)), z1, acc);
        acc = fmaf(__expf(v2 * fmaf(step, d2, 1.f)), z2, acc);
        acc = fmaf(__expf(v3 * fmaf(step, d3, 1.f)), z3, acc);
    }
    for (; n < NN; n += 8) {
        float4 cn = packb[n];
        float dot = cm.x*cn.x + cm.y*cn.y + cm.z*cn.z + cm.w*cn.w;
        float e = __expf(Cb[(size_t)n*NN + m] * fmaf(step, dot, 1.f));
        acc = fmaf(e, Zb[n], acc);
    }

    __shared__ float part[8][64];
    part[rg][c] = acc;
    __syncthreads();
    if (tid < 64) {
        float r = part[0][c] + part[1][c] + part[2][c] + part[3][c]
                + part[4][c] + part[5][c] + part[6][c] + part[7][c];
        float decay = *decay_p;
        float cprev = g_ccur[b*NN + m];
        float sig = 1.f / (1.f + __expf(-(r - 1.f)));
        float cnew = cprev * (1.f - decay*sig);
        g_ccur[b*NN + m] = cnew;
        float4 p = g_cpack[b*NN + m];
        if      (t == 0) p.x = cnew;
        else if (t == 1) p.y = cnew;
        else if (t == 2) p.z = cnew;
        else             p.w = cnew;
        g_cpack[b*NN + m] = p;
    }
}

// ============================================================
// K5: final attention. exp recomputed from compat in-tile;
// Z fused into accumulation (zrun per row, redundant per tx).
// AV[n] = (Σ_m e(n,m)·V[m]) / (Σ_m e(n,m)).
// ============================================================
__global__ void __launch_bounds__(256) k5_EV(const float* __restrict__ step_p) {
    __shared__ float Es[64][68];
    __shared__ float Vs[64][68];
    __shared__ float4 crp[64];
    int b = blockIdx.y;
    int tr = blockIdx.x;
    int r0 = tr * 64;
    int t = threadIdx.x, tx = t & 15, ty = t >> 4;
    float step = *step_p;

    if (t < 64) crp[t] = g_cpack[b*NN + r0 + t];

    float acc[4][4];
    #pragma unroll
    for (int i = 0; i < 4; i++)
        #pragma unroll
        for (int j = 0; j < 4; j++) acc[i][j] = 0.f;
    float zrun[4] = {0.f, 0.f, 0.f, 0.f};

    const float* Cb = g_compat + (size_t)b*NN*NN;
    const float* Vb = g_V + (size_t)b*NN*DK;
    __syncthreads();                        // crp visible

    const int cload = t & 63;               // this thread's column in load phase
    for (int mt = 0; mt <= tr; mt++) {
        int m0 = mt * 64;
        bool diag = (mt == tr);
        float4 cc = g_cpack[b*NN + m0 + cload];
        #pragma unroll
        for (int i = 0; i < 16; i++) {
            int idx = t + i*256;
            int r = idx >> 6, c = idx & 63;  // c == cload
            float4 cr = crp[r];
            float dot = cr.x*cc.x + cr.y*cc.y + cr.z*cc.z + cr.w*cc.w;
            float e;
            if (diag && c > r) e = 0.f;
            else e = __expf(Cb[(size_t)(r0+r)*NN + m0 + c] * fmaf(step, dot, 1.f));
            Es[r][c] = e;
            Vs[r][c] = Vb[(size_t)(m0+r)*DK + c];
        }
        __syncthreads();
        #pragma unroll 4
        for (int k = 0; k < 64; k += 4) {
            float4 e0 = *reinterpret_cast<const float4*>(&Es[ty*4+0][k]);
            float4 e1 = *reinterpret_cast<const float4*>(&Es[ty*4+1][k]);
            float4 e2 = *reinterpret_cast<const float4*>(&Es[ty*4+2][k]);
            float4 e3 = *reinterpret_cast<const float4*>(&Es[ty*4+3][k]);
            float er[4][4] = {{e0.x,e0.y,e0.z,e0.w},{e1.x,e1.y,e1.z,e1.w},
                              {e2.x,e2.y,e2.z,e2.w},{e3.x,e3.y,e3.z,e3.w}};
            #pragma unroll
            for (int i = 0; i < 4; i++)
                zrun[i] += (er[i][0] + er[i][1]) + (er[i][2] + er[i][3]);
            #pragma unroll
            for (int q = 0; q < 4; q++) {
                float4 v = *reinterpret_cast<const float4*>(&Vs[k+q][tx*4]);
                float vr[4] = {v.x, v.y, v.z, v.w};
                #pragma unroll
                for (int i = 0; i < 4; i++)
                    #pragma unroll
                    for (int j = 0; j < 4; j++)
                        acc[i][j] = fmaf(er[i][q], vr[j], acc[i][j]);
            }
        }
        __syncthreads();
    }
    #pragma unroll
    for (int i = 0; i < 4; i++) {
        int row = b*NN + r0 + ty*4 + i;
        float zi = 1.f / zrun[i];
        *reinterpret_cast<float4*>(&g_AV[(size_t)row*DK + tx*4]) =
            make_float4(acc[i][0]*zi, acc[i][1]*zi, acc[i][2]*zi, acc[i][3]*zi);
    }
}

// ============================================================
// K6: out = alpha * (AV @ wo^T). 128x128 tiles, 8x8 acc.
// ============================================================
__global__ void __launch_bounds__(256) k6_out(const float* __restrict__ wo,
        const float* __restrict__ mix_p, float* __restrict__ out) {
    __shared__ float As[32][132];
    __shared__ float Ws[32][132];
    int t = threadIdx.x, tx = t & 15, ty = t >> 4;
    int r0 = blockIdx.y * 128, c0 = blockIdx.x * 128;

    float acc[8][8];
    #pragma unroll
    for (int i = 0; i < 8; i++)
        #pragma unroll
        for (int j = 0; j < 8; j++) acc[i][j] = 0.f;

    for (int kc = 0; kc < 2; kc++) {
        int kb0 = kc*32;
        #pragma unroll
        for (int i = 0; i < 16; i++) {
            int idx = t + i*256;
            int r = idx >> 5, kk = idx & 31;
            As[kk][r] = g_AV[(size_t)(r0+r)*DK + kb0 + kk];
            Ws[kk][r] = wo[(size_t)(c0+r)*DK + kb0 + kk];
        }
        __syncthreads();
        #pragma unroll
        for (int k = 0; k < 32; k++) {
            float4 aa = *reinterpret_cast<const float4*>(&As[k][ty*4]);
            float4 ab = *reinterpret_cast<const float4*>(&As[k][64 + ty*4]);
            float4 wa = *reinterpret_cast<const float4*>(&Ws[k][tx*4]);
            float4 wb = *reinterpret_cast<const float4*>(&Ws[k][64 + tx*4]);
            float xr[8] = {aa.x,aa.y,aa.z,aa.w, ab.x,ab.y,ab.z,ab.w};
            float wr[8] = {wa.x,wa.y,wa.z,wa.w, wb.x,wb.y,wb.z,wb.w};
            #pragma unroll
            for (int i = 0; i < 8; i++)
                #pragma unroll
                for (int j = 0; j < 8; j++)
                    acc[i][j] = fmaf(xr[i], wr[j], acc[i][j]);
        }
        __syncthreads();
    }
    float alpha = 0.2f / (1.f + __expf(-mix_p[0]));
    #pragma unroll
    for (int i = 0; i < 8; i++) {
        int r = r0 + (i < 4 ? ty*4 + i : 64 + ty*4 + (i-4));
        *reinterpret_cast<float4*>(&out[(size_t)r*DD + c0 + tx*4]) =
            make_float4(acc[i][0]*alpha, acc[i][1]*alpha, acc[i][2]*alpha, acc[i][3]*alpha);
        *reinterpret_cast<float4*>(&out[(size_t)r*DD + c0 + 64 + tx*4]) =
            make_float4(acc[i][4]*alpha, acc[i][5]*alpha, acc[i][6]*alpha, acc[i][7]*alpha);
    }
}

// ============================================================
extern "C" void kernel_launch(void* const* d_in, const int* in_sizes, int n_in,
                              void* d_out, int out_size) {
    const float* X       = (const float*)d_in[0];
    const float* w1      = (const float*)d_in[2];
    const float* b1      = (const float*)d_in[3];
    const float* w2      = (const float*)d_in[4];
    const float* b2      = (const float*)d_in[5];
    const float* wq      = (const float*)d_in[6];
    const float* wk      = (const float*)d_in[7];
    const float* wc      = (const float*)d_in[8];
    const float* bc      = (const float*)d_in[9];
    const float* step_p  = (const float*)d_in[10];
    const float* decay_p = (const float*)d_in[11];
    const float* wv      = (const float*)d_in[12];
    const float* wo      = (const float*)d_in[13];
    const float* mix_p   = (const float*)d_in[14];
    float* out = (float*)d_out;

    k1_gemm<<<BN/128, 256>>>(X, w1, b1, wv);
    k2_feat<<<BN/8, 256>>>(w2, b2, wq, wk, wc, bc);
    k3_compat<<<dim3(NN/128, NN/128, BB), 256>>>();
    for (int t = 0; t < NSTEPS; t++) {
        kA_Z<<<BN, 256>>>(step_p);
        kB_recv<<<dim3(NN/64, BB), 512>>>(t, step_p, decay_p);
    }
    k5_EV<<<dim3(NN/64, BB), 256>>>(step_p);
    k6_out<<<dim3(DD/128, BN/128), 256>>>(wo, mix_p, out);
}